// round 6
// baseline (speedup 1.0000x reference)
#include <cuda_runtime.h>
#include <math.h>
#include <stdint.h>

#define NSNR 2048
#define NT   4096
#define NP   100
#define NI   99
#define TPB  256
#define EPT  (NT / TPB)    // 16 consecutive elements per thread
#define NWARP (TPB / 32)
#define NACC 32
#define SWZ(c) ((c) ^ (((c) >> 3) & 3))   // 16B-chunk XOR swizzle

__device__ double       g_acc[NACC];   // zero-init; reset by last block each run
__device__ unsigned int g_ticket;      // self-resetting via atomicInc wrap

// Precomputed Thomas forward-elimination multipliers for tri(1,4,1), n=98.
struct CpTab { float v[98]; };
static constexpr CpTab make_cp() {
    CpTab t{};
    double c = 0.25;
    t.v[0] = (float)c;
    for (int i = 1; i < 98; i++) { c = 1.0 / (4.0 - c); t.v[i] = (float)c; }
    return t;
}
__constant__ CpTab d_cp = make_cp();

// ---------------------------------------------------------------------------
__device__ __forceinline__ uint32_t smem_u32(const void* p) {
    return (uint32_t)__cvta_generic_to_shared(p);
}
__device__ __forceinline__ void cp_async16(uint32_t saddr, const void* gptr) {
    asm volatile("cp.async.cg.shared.global [%0], [%1], 16;" :: "r"(saddr), "l"(gptr));
}
__device__ __forceinline__ void cp_commit() {
    asm volatile("cp.async.commit_group;");
}
template <int N> __device__ __forceinline__ void cp_wait() {
    asm volatile("cp.async.wait_group %0;" :: "n"(N));
}

// scalar element read from a chunk-swizzled buffer
__device__ __forceinline__ float ld_elem(const float4* sv, int e) {
    return reinterpret_cast<const float*>(sv)[4 * SWZ(e >> 2) + (e & 3)];
}

// Block-wide exclusive scan of one float per thread. Contains __syncthreads.
__device__ __forceinline__ float block_scan_excl(float v, float* warp_sums, float* total) {
    int lane = threadIdx.x & 31, wid = threadIdx.x >> 5;
    float x = v;
#pragma unroll
    for (int o = 1; o < 32; o <<= 1) {
        float y = __shfl_up_sync(0xffffffffu, x, o);
        if (lane >= o) x += y;
    }
    if (lane == 31) warp_sums[wid] = x;
    __syncthreads();
    if (wid == 0) {
        float w = (lane < NWARP) ? warp_sums[lane] : 0.0f;
#pragma unroll
        for (int o = 1; o < NWARP; o <<= 1) {
            float y = __shfl_up_sync(0xffffffffu, w, o);
            if (lane >= o) w += y;
        }
        if (lane < NWARP) warp_sums[lane] = w;
    }
    __syncthreads();
    float excl = (x - v) + (wid ? warp_sums[wid - 1] : 0.0f);
    *total = warp_sums[NWARP - 1];
    return excl;
}

// Blocked read of this thread's 16 |elements| from a swizzled buffer + the
// boundary element (last element of previous thread's block).
__device__ __forceinline__ float read_block(const float4* sv, float fa[EPT]) {
    const int tid = threadIdx.x;
#pragma unroll
    for (int q = 0; q < 4; q++) {
        float4 v = sv[SWZ(4 * tid + q)];
        fa[4 * q + 0] = v.x;
        fa[4 * q + 1] = v.y;
        fa[4 * q + 2] = v.z;
        fa[4 * q + 3] = v.w;
    }
    return (tid == 0) ? 0.0f : ld_elem(sv, EPT * tid - 1);
}

// ---------------------------------------------------------------------------
__global__ void __launch_bounds__(TPB, 6) wasserstein_kernel(
    const float* __restrict__ f, const float* __restrict__ obs,
    const float* __restrict__ t, float* __restrict__ out)
{
    __shared__ float4 sA4[NT / 4];     // |obs| (swizzled) -> overwritten by CDF
    __shared__ float4 sF4[NT / 4];     // |f|   (swizzled)
    __shared__ float4 scf4[NP];        // spline coeffs (a,b,c,d)
    __shared__ float  sQ[NP];
    __shared__ float  sM[NP];
    __shared__ float  sdp[98];
    __shared__ float  warp_sums[NWARP];
    __shared__ float  red[NWARP];

    const int   row = blockIdx.x;
    const int   tid = threadIdx.x;
    const float dt  = t[1] - t[0];
    const float hd  = 0.5f * dt;

    // ---- issue ALL DRAM traffic up front (striped, coalesced, swizzled) ----
    {
        const float4* go = reinterpret_cast<const float4*>(obs + (size_t)row * NT);
        const float4* gf = reinterpret_cast<const float4*>(f   + (size_t)row * NT);
        uint32_t sa = smem_u32(sA4);
        uint32_t sf = smem_u32(sF4);
#pragma unroll
        for (int i = 0; i < 4; i++) {
            int j = tid + TPB * i;
            cp_async16(sa + 16u * SWZ(j), go + j);
        }
        cp_commit();
#pragma unroll
        for (int i = 0; i < 4; i++) {
            int j = tid + TPB * i;
            cp_async16(sf + 16u * SWZ(j), gf + j);
        }
        cp_commit();
    }

    // ================= Phase A: obs -> spline coefficients =================
    cp_wait<1>();
    __syncthreads();

    float fa[EPT];
    // take |.| in place is folded into reads below (cp.async stored raw)
    {
        float prev = read_block(sA4, fa);
        prev = fabsf(prev);
#pragma unroll
        for (int k = 0; k < EPT; k++) fa[k] = fabsf(fa[k]);

        float run = 0.0f;
        {
            float p = prev;
#pragma unroll
            for (int k = 0; k < EPT; k++) {
                float cur = fa[k];
                float e = (tid == 0 && k == 0) ? 0.0f : hd * (cur + p);
                run += e;
                p = cur;
            }
        }
        float total;
        float excl = block_scan_excl(run, warp_sums, &total);
        if (tid == 0) red[0] = total;          // stash row total for search

        // overwrite sA4 with element CDF (blocked STS.128, conflict-free)
        {
            float S = excl, p = prev;
#pragma unroll
            for (int q = 0; q < 4; q++) {
                float4 o;
#pragma unroll
                for (int k = 0; k < 4; k++) {
                    float cur = fa[4 * q + k];
                    float e = (tid == 0 && q == 0 && k == 0) ? 0.0f : hd * (cur + p);
                    S += e;
                    p = cur;
                    ((float*)&o)[k] = S;
                }
                sA4[SWZ(4 * tid + q)] = o;
            }
        }
    }
    __syncthreads();

    // inverse CDF at 100 quantiles (binary search over swizzled CDF)
    if (tid < NP) {
        float total = red[0];
        float target = ((float)tid / 99.0f) * total;
        int lo = 0, hi = NT - 1;
        while (lo < hi) {
            int mid = (lo + hi + 1) >> 1;
            if (ld_elem(sA4, mid) <= target) lo = mid; else hi = mid - 1;
        }
        int j = min(lo, NT - 2);
        float Sj  = ld_elem(sA4, j);
        float Sj1 = ld_elem(sA4, j + 1);
        float den = Sj1 - Sj;
        float q = (float)j * dt;
        if (den > 0.0f) q += (target - Sj) * dt / den;
        sQ[tid] = q;
    }
    __syncthreads();

    // u_i = rhs_i * cp_i in parallel (98 threads)
    if (tid < 98) {
        const float S6 = 6.0f * 9801.0f;   // 6 / h^2
        float rhs = S6 * (sQ[tid + 2] - 2.0f * sQ[tid + 1] + sQ[tid]);
        sdp[tid] = rhs * d_cp.v[tid];
    }
    __syncthreads();

    // serial Thomas recurrences (single FFMA chains)
    if (tid == 0) {
        float dp = sdp[0];
#pragma unroll 7
        for (int i = 1; i < 98; i++) {
            dp = fmaf(-d_cp.v[i], dp, sdp[i]);
            sdp[i] = dp;
        }
        sM[0] = 0.0f;
        sM[NP - 1] = 0.0f;
        float mnext = sdp[97];
        sM[98] = mnext;
#pragma unroll 7
        for (int i = 96; i >= 0; i--) {
            mnext = fmaf(-d_cp.v[i], mnext, sdp[i]);
            sM[i + 1] = mnext;
        }
    }
    __syncthreads();

    if (tid < NI) {
        const float H    = (float)(1.0 / 99.0);
        const float invH = 99.0f;
        float Mi = sM[tid], Mi1 = sM[tid + 1];
        float4 c;
        c.x = sQ[tid];
        c.y = (sQ[tid + 1] - sQ[tid]) * invH - H * (2.0f * Mi + Mi1) * (1.0f / 6.0f);
        c.z = Mi * 0.5f;
        c.w = (Mi1 - Mi) * (invH / 6.0f);
        scf4[tid] = c;
    }

    // ================= Phase B: f -> loss contribution =================
    cp_wait<0>();
    __syncthreads();     // also publishes scf4

    float prev = read_block(sF4, fa);
    prev = fabsf(prev);
#pragma unroll
    for (int k = 0; k < EPT; k++) fa[k] = fabsf(fa[k]);

    float run = 0.0f;
    {
        float p = prev;
#pragma unroll
        for (int k = 0; k < EPT; k++) {
            float cur = fa[k];
            float e = (tid == 0 && k == 0) ? 0.0f : hd * (cur + p);
            run += e;
            p = cur;
        }
    }
    float total;
    float excl = block_scan_excl(run, warp_sums, &total);

    const float invT = 1.0f / total;
    float gsum = 0.0f;
    {
        float S = excl, p = prev;
        int   idx = -1;
        float4 cf = make_float4(0.f, 0.f, 0.f, 0.f);
#pragma unroll
        for (int k = 0; k < EPT; k++) {
            int j = EPT * tid + k;
            float cur = fa[k];
            float e = (tid == 0 && k == 0) ? 0.0f : hd * (cur + p);
            S += e;
            p = cur;

            float xi = fminf(S * invT, 1.0f);
            int ki = min((int)(xi * 99.0f), NI - 1);
            if (ki != idx) { idx = ki; cf = scf4[ki]; }     // rare (monotone F)
            float dx = xi - (float)idx * (float)(1.0 / 99.0);
            float val = cf.x + dx * (cf.y + dx * (cf.z + dx * cf.w));
            float diff = (float)j * dt - val;
            float g = diff * diff * (cur * invT);
            gsum += g;
            if (j == 0 || j == NT - 1) gsum -= 0.5f * g;    // trapezoid edges
        }
    }

#pragma unroll
    for (int o = 16; o; o >>= 1) gsum += __shfl_down_sync(0xffffffffu, gsum, o);
    if ((tid & 31) == 0) red[tid >> 5] = gsum;
    __syncthreads();

    if (tid == 0) {
        float s = 0.0f;
#pragma unroll
        for (int w = 0; w < NWARP; w++) s += red[w];
        double my = (double)(dt * s);
        atomicAdd(&g_acc[row & (NACC - 1)], my);
        __threadfence();
        unsigned tk = atomicInc(&g_ticket, NSNR - 1);   // wraps to 0 automatically
        if (tk == NSNR - 1) {
            double tot = 0.0;
#pragma unroll
            for (int w = 0; w < NACC; w++) { tot += g_acc[w]; g_acc[w] = 0.0; }
            out[0] = (float)tot;
        }
    }
}

// ---------------------------------------------------------------------------
extern "C" void kernel_launch(void* const* d_in, const int* in_sizes, int n_in,
                              void* d_out, int out_size)
{
    const float* f   = (const float*)d_in[0];
    const float* obs = (const float*)d_in[1];
    const float* t   = (const float*)d_in[2];

    wasserstein_kernel<<<NSNR, TPB>>>(f, obs, t, (float*)d_out);
}